// round 3
// baseline (speedup 1.0000x reference)
#include <cuda_runtime.h>
#include <math.h>

#define BB 64
#define SS 256
#define II 512
#define HH 80
#define TT 600
#define CC 512
#define XD 592          /* HH + II */
#define KCAT 1104       /* XD + CC */
#define NCOLS 2048      /* 1024 rz-merged + 512 xn + 512 hn */
#define GRID 128
#define NTHR 256

// ---------------- device scratch ----------------
__device__ float g_xc[BB][KCAT];      // [frame 80 | prev 512 | state 512]
__device__ float g_wcat[NCOLS][KCAT]; // repacked GRU weights
__device__ float g_g[BB][NCOLS];      // GEMM output (pre-gate)
__device__ float g_t1[BB][CC];
__device__ float g_dk[BB][168];
__device__ float g_energy[BB][SS];
__device__ float g_alpha[BB][SS];
__device__ unsigned g_bar;

__device__ __forceinline__ float sig_fast(float x) { return 1.f / (1.f + __expf(-x)); }
__device__ __forceinline__ float tanh_fast(float x) {
    float e = __expf(2.f * x);
    return 1.f - 2.f / (e + 1.f);
}

// grid-wide barrier: all 128 blocks co-resident (1 block/SM guaranteed)
__device__ __forceinline__ void gsync(unsigned& gen) {
    gen += GRID;
    __syncthreads();
    if (threadIdx.x == 0) {
        __threadfence();
        atomicAdd(&g_bar, 1u);
        while (*(volatile unsigned*)&g_bar < gen) __nanosleep(32);
        __threadfence();
    }
    __syncthreads();
}

// ---------------- init: reset barrier/state, repack weights ----------------
__global__ void k_init(const float* __restrict__ wi, const float* __restrict__ wh) {
    int idx = blockIdx.x * blockDim.x + threadIdx.x;
    if (idx == 0) g_bar = 0u;
    if (idx < BB * CC) {
        int b = idx >> 9, c = idx & 511;
        g_xc[b][XD + c] = 0.f;
    }
    int stride = gridDim.x * blockDim.x;
    for (size_t i = idx; i < (size_t)NCOLS * KCAT; i += stride) {
        int j = (int)(i / KCAT), k = (int)(i % KCAT);
        float v;
        if (j < 1024)      v = (k < XD) ? wi[(size_t)j * XD + k] : wh[(size_t)j * CC + (k - XD)];
        else if (j < 1536) v = (k < XD) ? wi[(size_t)j * XD + k] : 0.f;
        else               v = (k < XD) ? 0.f : wh[(size_t)(j - 512) * CC + (k - XD)];
        g_wcat[j][k] = v;
    }
}

// ---------------- the persistent kernel ----------------
__global__ void __launch_bounds__(NTHR)
k_persist(const float* __restrict__ enc, const float* __restrict__ gt,
          const float* __restrict__ mask,
          const float* __restrict__ bi, const float* __restrict__ bh,
          const float* __restrict__ w1, const float* __restrict__ b1,
          const float* __restrict__ w2,
          const float* __restrict__ lw, const float* __restrict__ lp,
          const float* __restrict__ dw, const float* __restrict__ db,
          const float* __restrict__ aw, const float* __restrict__ prior,
          float* __restrict__ out) {
    __shared__ float sm[4608];
    unsigned gen = 0;
    int bid = blockIdx.x, tid = threadIdx.x;
    int lane = tid & 31, wrp = tid >> 5;

    for (int t = 0;; t++) {
        // ================= Phase A: softmax -> alpha -> prev-context =========
        {
            int b = bid >> 1, half = bid & 1;
            float* s_alpha = sm;        // 256
            float* s_red   = sm + 256;  // 8
            float* s_part  = sm + 272;  // 1024 (16B aligned: 272*4=1088)

            float a;
            if (t == 0) {
                a = (tid == 0) ? 1.f : 0.f;
            } else {
                float e = __ldcg(&g_energy[b][tid]);
                float m = e;
                #pragma unroll
                for (int o = 16; o; o >>= 1) m = fmaxf(m, __shfl_xor_sync(0xffffffffu, m, o));
                if (lane == 0) s_red[wrp] = m;
                __syncthreads();
                float bm = s_red[0];
                #pragma unroll
                for (int i = 1; i < 8; i++) bm = fmaxf(bm, s_red[i]);
                float p = __expf(e - bm);
                float ws = p;
                #pragma unroll
                for (int o = 16; o; o >>= 1) ws += __shfl_xor_sync(0xffffffffu, ws, o);
                __syncthreads();
                if (lane == 0) s_red[wrp] = ws;
                __syncthreads();
                float tot = 0.f;
                #pragma unroll
                for (int i = 0; i < 8; i++) tot += s_red[i];
                a = p / tot;
                if (half == 0) out[((size_t)b * TT + (t - 1)) * SS + tid] = a;
            }
            s_alpha[tid] = a;
            if (half == 0) g_alpha[b][tid] = a;
            __syncthreads();

            if (t == TT) break;   // final softmax done; all blocks exit

            if (half == 0 && tid < HH)
                g_xc[b][tid] = gt[((size_t)b * TT + t) * HH + tid];

            int cs = tid & 63, sl = tid >> 6;
            int c = half * 256 + cs * 4;
            const float* ep = enc + (size_t)b * SS * II + c;
            float4 acc = make_float4(0.f, 0.f, 0.f, 0.f);
            #pragma unroll 8
            for (int s = sl * 64; s < sl * 64 + 64; s++) {
                float av = s_alpha[s];
                float4 ev = *(const float4*)&ep[(size_t)s * II];
                acc.x = fmaf(av, ev.x, acc.x);
                acc.y = fmaf(av, ev.y, acc.y);
                acc.z = fmaf(av, ev.z, acc.z);
                acc.w = fmaf(av, ev.w, acc.w);
            }
            *(float4*)&s_part[(sl * 64 + cs) * 4] = acc;
            __syncthreads();
            if (tid < 64) {
                float4 r = *(const float4*)&s_part[tid * 4];
                #pragma unroll
                for (int ks = 1; ks < 4; ks++) {
                    float4 v = *(const float4*)&s_part[(ks * 64 + tid) * 4];
                    r.x += v.x; r.y += v.y; r.z += v.z; r.w += v.w;
                }
                *(float4*)&g_xc[b][HH + half * 256 + tid * 4] = r;
            }
        }
        gsync(gen);

        // ================= Phase B: GRU GEMM (2048 cols x 64 b, K=1104) ======
        {
            int col0 = bid * 16;
            float* xs = sm;          // 48*68 = 3264
            float* ws = sm + 3264;   // 48*20 = 960
            int ks = tid >> 6, r = tid & 63, ty = r >> 2, tx = r & 3;
            float a00=0,a01=0,a02=0,a03=0, a10=0,a11=0,a12=0,a13=0;
            float a20=0,a21=0,a22=0,a23=0, a30=0,a31=0,a32=0,a33=0;

            for (int kc = 0; kc < KCAT; kc += 48) {
                __syncthreads();
                #pragma unroll
                for (int it = 0; it < 12; it++) {
                    int idx = tid + it * 256;
                    int rr = idx / 48, kk = idx - rr * 48;
                    xs[kk * 68 + rr] = __ldcg(&g_xc[rr][kc + kk]);
                }
                #pragma unroll
                for (int it = 0; it < 3; it++) {
                    int idx = tid + it * 256;
                    int rr = idx / 48, kk = idx - rr * 48;
                    ws[kk * 20 + rr] = g_wcat[col0 + rr][kc + kk];
                }
                __syncthreads();
                #pragma unroll
                for (int kk = 0; kk < 12; kk++) {
                    int k = ks * 12 + kk;
                    float4 xv = *(const float4*)&xs[k * 68 + ty * 4];
                    float4 wv = *(const float4*)&ws[k * 20 + tx * 4];
                    a00 = fmaf(xv.x, wv.x, a00); a01 = fmaf(xv.x, wv.y, a01);
                    a02 = fmaf(xv.x, wv.z, a02); a03 = fmaf(xv.x, wv.w, a03);
                    a10 = fmaf(xv.y, wv.x, a10); a11 = fmaf(xv.y, wv.y, a11);
                    a12 = fmaf(xv.y, wv.z, a12); a13 = fmaf(xv.y, wv.w, a13);
                    a20 = fmaf(xv.z, wv.x, a20); a21 = fmaf(xv.z, wv.y, a21);
                    a22 = fmaf(xv.z, wv.z, a22); a23 = fmaf(xv.z, wv.w, a23);
                    a30 = fmaf(xv.w, wv.x, a30); a31 = fmaf(xv.w, wv.y, a31);
                    a32 = fmaf(xv.w, wv.z, a32); a33 = fmaf(xv.w, wv.w, a33);
                }
            }
            __syncthreads();
            float* red = sm;  // 4*64*17 = 4352
            int base = (ks * 64 + r) * 17;
            red[base+0]=a00; red[base+1]=a01; red[base+2]=a02; red[base+3]=a03;
            red[base+4]=a10; red[base+5]=a11; red[base+6]=a12; red[base+7]=a13;
            red[base+8]=a20; red[base+9]=a21; red[base+10]=a22; red[base+11]=a23;
            red[base+12]=a30; red[base+13]=a31; red[base+14]=a32; red[base+15]=a33;
            __syncthreads();
            #pragma unroll
            for (int u = 0; u < 4; u++) {
                int o = tid + u * 256;
                int rr = o >> 4, e = o & 15;
                float v = red[rr * 17 + e] + red[(64 + rr) * 17 + e]
                        + red[(128 + rr) * 17 + e] + red[(192 + rr) * 17 + e];
                int tyy = rr >> 2, txx = rr & 3, i = e >> 2, j = e & 3;
                g_g[tyy * 4 + i][col0 + txx * 4 + j] = v;
            }
        }
        gsync(gen);

        // ================= Phase C: gates -> new state ========================
        {
            int idx = bid * 256 + tid;
            int b = idx >> 9, c = idx & 511;
            float xr = __ldcg(&g_g[b][c]);
            float xz = __ldcg(&g_g[b][512 + c]);
            float xn = __ldcg(&g_g[b][1024 + c]);
            float hn = __ldcg(&g_g[b][1536 + c]);
            float rg = sig_fast(xr + bi[c] + bh[c]);
            float zg = sig_fast(xz + bi[512 + c] + bh[512 + c]);
            float ng = tanh_fast(xn + bi[1024 + c] + rg * (hn + bh[1024 + c]));
            float st = __ldcg(&g_xc[b][XD + c]);
            g_xc[b][XD + c] = (1.f - zg) * ng + zg * st;
        }
        gsync(gen);

        // ================= Phase D: t1 = tanh(q @ W1^T + b1) ==================
        {
            int col0 = bid * 4;
            float* xs = sm;          // 32*68 = 2176
            float* ws = sm + 2176;   // 32*4 = 128
            int ks = tid >> 6, r = tid & 63, ty = r >> 2, tx = r & 3;
            float ac0 = 0, ac1 = 0, ac2 = 0, ac3 = 0;
            for (int kc = 0; kc < CC; kc += 32) {
                __syncthreads();
                #pragma unroll
                for (int it = 0; it < 8; it++) {
                    int idx = tid + it * 256;
                    int rr = idx >> 5, kk = idx & 31;
                    xs[kk * 68 + rr] = __ldcg(&g_xc[rr][XD + kc + kk]);
                }
                if (tid < 128) {
                    int rr = tid >> 5, kk = tid & 31;
                    ws[kk * 4 + rr] = w1[(size_t)(col0 + rr) * CC + kc + kk];
                }
                __syncthreads();
                #pragma unroll
                for (int kk = 0; kk < 8; kk++) {
                    int k = ks * 8 + kk;
                    float4 xv = *(const float4*)&xs[k * 68 + ty * 4];
                    float wv = ws[k * 4 + tx];
                    ac0 = fmaf(xv.x, wv, ac0); ac1 = fmaf(xv.y, wv, ac1);
                    ac2 = fmaf(xv.z, wv, ac2); ac3 = fmaf(xv.w, wv, ac3);
                }
            }
            __syncthreads();
            float* red = sm;  // 4*64*5 = 1280
            int base = (ks * 64 + r) * 5;
            red[base + 0] = ac0; red[base + 1] = ac1;
            red[base + 2] = ac2; red[base + 3] = ac3;
            __syncthreads();
            {
                int rr = tid >> 2, i = tid & 3;
                float v = red[rr * 5 + i] + red[(64 + rr) * 5 + i]
                        + red[(128 + rr) * 5 + i] + red[(192 + rr) * 5 + i];
                int tyy = rr >> 2, txx = rr & 3;
                int b = tyy * 4 + i, c = col0 + txx;
                g_t1[b][c] = tanh_fast(v + b1[c]);
            }
        }
        gsync(gen);

        // ================= Phase E: dkern = t1 @ W2^T (168 cols) ==============
        {
            int col0 = bid * 2;
            bool active = (col0 < 168);
            float* xs = sm;          // 32*68
            float* ws = sm + 2176;   // 32*2
            int ks = tid >> 5, r = tid & 31, ty = r >> 1, tx = r & 1;
            float ac0 = 0, ac1 = 0, ac2 = 0, ac3 = 0;
            for (int kc = 0; kc < CC; kc += 32) {
                __syncthreads();
                #pragma unroll
                for (int it = 0; it < 8; it++) {
                    int idx = tid + it * 256;
                    int rr = idx >> 5, kk = idx & 31;
                    xs[kk * 68 + rr] = __ldcg(&g_t1[rr][kc + kk]);
                }
                if (active && tid < 64) {
                    int rr = tid >> 5, kk = tid & 31;
                    ws[kk * 2 + rr] = w2[(size_t)(col0 + rr) * CC + kc + kk];
                }
                __syncthreads();
                if (active) {
                    #pragma unroll
                    for (int kk = 0; kk < 4; kk++) {
                        int k = ks * 4 + kk;
                        float4 xv = *(const float4*)&xs[k * 68 + ty * 4];
                        float wv = ws[k * 2 + tx];
                        ac0 = fmaf(xv.x, wv, ac0); ac1 = fmaf(xv.y, wv, ac1);
                        ac2 = fmaf(xv.z, wv, ac2); ac3 = fmaf(xv.w, wv, ac3);
                    }
                }
            }
            __syncthreads();
            float* red = sm;  // 8*32*5 = 1280
            if (active) {
                int base = (ks * 32 + r) * 5;
                red[base + 0] = ac0; red[base + 1] = ac1;
                red[base + 2] = ac2; red[base + 3] = ac3;
            }
            __syncthreads();
            if (active && tid < 128) {
                int rr = tid >> 2, i = tid & 3;
                float v = 0.f;
                #pragma unroll
                for (int k8 = 0; k8 < 8; k8++) v += red[(k8 * 32 + rr) * 5 + i];
                int tyy = rr >> 1, txx = rr & 1;
                g_dk[tyy * 4 + i][col0 + txx] = v;
            }
        }
        gsync(gen);

        // ================= Phase F: convs + score + energy ====================
        {
            int b = bid >> 1, shalf = bid & 1, s0 = shalf * 128;
            float* s_a   = sm;          // 148
            float* s_lw  = sm + 148;    // 168
            float* s_dkk = sm + 316;    // 168
            float* s_ft  = sm + 484;    // 128*16 = 2048
            float* s_pri = sm + 2532;   // 128
            float* s_en  = sm + 2660;   // 8*128 = 1024

            if (tid < 148) {
                int s = s0 - 10 + tid;
                s_a[tid] = (s >= 0 && s < SS) ? __ldcg(&g_alpha[b][s]) : 0.f;
            }
            if (tid < 168) {
                s_lw[tid]  = lw[tid];
                s_dkk[tid] = __ldcg(&g_dk[b][tid]);
            }
            __syncthreads();

            #pragma unroll
            for (int it = 0; it < 8; it++) {
                int idx = tid + it * 256;
                int l = idx & 15, si = idx >> 4;
                const float* wv = (l < 8) ? &s_lw[l * 21] : &s_dkk[(l - 8) * 21];
                float a = 0.f;
                #pragma unroll
                for (int k = 0; k < 21; k++) a = fmaf(s_a[si + k], wv[k], a);
                s_ft[si * 16 + l] = a;
            }
            if (tid < 128) {
                float a = 0.f;
                #pragma unroll
                for (int k = 0; k < 11; k++) a = fmaf(s_a[tid + k], prior[k], a);
                s_pri[tid] = a;
            }
            __syncthreads();

            int c = tid;
            float4 lp0 = *(const float4*)&lp[c * 8], lp1 = *(const float4*)&lp[c * 8 + 4];
            float4 dw0 = *(const float4*)&dw[c * 8], dw1 = *(const float4*)&dw[c * 8 + 4];
            float dbc = db[c], awc = aw[c];
            for (int si = 0; si < 128; si++) {
                float4 f0 = *(const float4*)&s_ft[si * 16 + 0];
                float4 f1 = *(const float4*)&s_ft[si * 16 + 4];
                float4 f2 = *(const float4*)&s_ft[si * 16 + 8];
                float4 f3 = *(const float4*)&s_ft[si * 16 + 12];
                float sc = dbc;
                sc = fmaf(lp0.x, f0.x, sc); sc = fmaf(lp0.y, f0.y, sc);
                sc = fmaf(lp0.z, f0.z, sc); sc = fmaf(lp0.w, f0.w, sc);
                sc = fmaf(lp1.x, f1.x, sc); sc = fmaf(lp1.y, f1.y, sc);
                sc = fmaf(lp1.z, f1.z, sc); sc = fmaf(lp1.w, f1.w, sc);
                sc = fmaf(dw0.x, f2.x, sc); sc = fmaf(dw0.y, f2.y, sc);
                sc = fmaf(dw0.z, f2.z, sc); sc = fmaf(dw0.w, f2.w, sc);
                sc = fmaf(dw1.x, f3.x, sc); sc = fmaf(dw1.y, f3.y, sc);
                sc = fmaf(dw1.z, f3.z, sc); sc = fmaf(dw1.w, f3.w, sc);
                float v = awc * tanh_fast(sc);
                #pragma unroll
                for (int o = 16; o; o >>= 1) v += __shfl_xor_sync(0xffffffffu, v, o);
                if (lane == 0) s_en[wrp * 128 + si] = v;
            }
            __syncthreads();
            if (tid < 128) {
                float e = 0.f;
                #pragma unroll
                for (int i = 0; i < 8; i++) e += s_en[i * 128 + tid];
                e += __logf(s_pri[tid] + 1e-5f);
                int s = s0 + tid;
                e = (mask[b * SS + s] > 0.f) ? e : -INFINITY;
                g_energy[b][s] = e;
            }
        }
        gsync(gen);
    }
}

extern "C" void kernel_launch(void* const* d_in, const int* in_sizes, int n_in,
                              void* d_out, int out_size) {
    const float* enc   = (const float*)d_in[0];
    const float* mask  = (const float*)d_in[1];
    const float* gt    = (const float*)d_in[2];
    const float* wi    = (const float*)d_in[3];
    const float* wh    = (const float*)d_in[4];
    const float* bi    = (const float*)d_in[5];
    const float* bh    = (const float*)d_in[6];
    const float* lw    = (const float*)d_in[7];
    const float* lp    = (const float*)d_in[8];
    const float* w1    = (const float*)d_in[9];
    const float* b1    = (const float*)d_in[10];
    const float* w2    = (const float*)d_in[11];
    const float* dw    = (const float*)d_in[12];
    const float* db    = (const float*)d_in[13];
    const float* aw    = (const float*)d_in[14];
    const float* prior = (const float*)d_in[15];
    float* out = (float*)d_out;

    k_init<<<512, 256>>>(wi, wh);
    k_persist<<<GRID, NTHR>>>(enc, gt, mask, bi, bh, w1, b1, w2,
                              lw, lp, dw, db, aw, prior, out);
}